// round 16
// baseline (speedup 1.0000x reference)
#include <cuda_runtime.h>
#include <cuda_fp16.h>
#include <cstdint>
#include <cfloat>

// Problem constants
#define NF    1024
#define BATCH 1024
#define HW    64
#define PIX   (HW * HW)     // 4096
#define PAD   3
#define PW    70            // padded side
#define PPIX  (PW * PW)     // 4900

// GEMM shape per CTA: D[128 batch, 40 out] = Xw[128, 112] x Mmat[112, 40]
#define KDIM   112          // 100 window pixels padded to 7 k16-steps
#define NDIM   40           // 36 conv outputs padded to 5 n8-frags
#define MCHUNK 128          // batches per CTA
#define XW_STRIDE 136       // halves per Xw row (272 B: 256 data + 16 pad
                            //  -> ldmatrix row stride 68 banks, conflict-free)
#define MT_STRIDE 116       // halves per Mmat_T row (232 B)

// 10 MB scratch: zero-PADDED image, fp16, transposed to [padded_pixel][batch].
// __device__ globals are zero-initialized at module load (fp16 zero == 0x0000)
// and the transpose never writes the 3-wide border -> no bounds checks needed.
__device__ __half g_xh[(size_t)PPIX * BATCH];

// ---------------------------------------------------------------------------
// Kernel 1: transpose + fp32->fp16 convert.  X [B, 4096] -> g_xh interior.
// ---------------------------------------------------------------------------
__global__ void xt_transpose_kernel(const float* __restrict__ X) {
    __shared__ float tile[32][65];          // [pixel_local][batch_local]
    const int p0 = blockIdx.x * 32;
    const int b0 = blockIdx.y * 64;
    const int tx = threadIdx.x;             // block (32, 8)
    const int ty = threadIdx.y;

#pragma unroll
    for (int k = 0; k < 64; k += 8)         // coalesced 128B loads
        tile[tx][ty + k] = X[(size_t)(b0 + ty + k) * PIX + (p0 + tx)];
    __syncthreads();

    const int w = ty;
#pragma unroll
    for (int i = 0; i < 4; i++) {
        const int pl = w * 4 + i;
        const int p  = p0 + pl;
        const int y  = p >> 6, x = p & 63;
        const __half2 v = __floats2half2_rn(tile[pl][2 * tx],
                                            tile[pl][2 * tx + 1]);
        *(__half2*)(g_xh + (size_t)((y + PAD) * PW + (x + PAD)) * BATCH
                         + b0 + 2 * tx) = v;
    }
}

__device__ __forceinline__ uint32_t smem_u32(const void* p) {
    uint32_t a;
    asm("{ .reg .u64 t; cvta.to.shared.u64 t, %1; cvt.u32.u64 %0, t; }"
        : "=r"(a) : "l"(p));
    return a;
}

// ---------------------------------------------------------------------------
// Kernel 2: tensor-core conv.  CTA = (filter f, batch-chunk of 128).
//   Xw SMEM tile [112 k][128 batch] copied coalesced from g_xh (rows 100-111
//   zero);  Mmat_T [40 n][112 k] built from the 25 weights.
//   4 warps x 32 batches: mma.sync.m16n8k16 f16f16-f32, A = Xw^T fragments
//   via ldmatrix.x4.trans, B = Mmat fragments via LDS.32.
//   Epilogue: fold the 36 conv outputs into the 2x2 maxpool (per-lane select
//   + quad shfl butterfly), add bias, one float4 store per batch row.
// ---------------------------------------------------------------------------
__global__ void __launch_bounds__(128) filters_mma_kernel(
    const float* __restrict__ W,      // [NF, 25]
    const float* __restrict__ bias,   // [NF]
    const int*   __restrict__ pos,    // [NF, 2]
    float*       __restrict__ out)    // [B, NF*4]
{
    __shared__ __align__(16) __half xw[KDIM * XW_STRIDE];   // 30464 B
    __shared__ __align__(16) __half mt[NDIM * MT_STRIDE];   //  9280 B

    const int tid   = threadIdx.x;
    const int f     = blockIdx.x;
    const int chunk = blockIdx.y;           // 8 chunks of 128 batches
    const int pi = __ldg(&pos[2 * f]);
    const int pj = __ldg(&pos[2 * f + 1]);

    // ---- Fill Xw: 112 rows x 16 granules of 16B (rows >= 100 are zero) ----
    const __half* gwin = g_xh + (size_t)(pi * PW + pj) * BATCH + chunk * MCHUNK;
#pragma unroll 2
    for (int e = tid; e < KDIM * 16; e += 128) {
        const int k = e >> 4, g = e & 15;
        float4 v = make_float4(0.f, 0.f, 0.f, 0.f);
        if (k < 100) {
            const int r = k / 10, c = k - 10 * r;
            v = *(const float4*)(gwin + (size_t)(r * PW + c) * BATCH + g * 8);
        }
        *(float4*)(xw + k * XW_STRIDE + g * 8) = v;
    }

    // ---- Build Mmat_T[n][k] = W[r-oy][c-ox] (0 outside support/pads) ----
#pragma unroll 2
    for (int e = tid; e < NDIM * KDIM; e += 128) {
        const int n = e / KDIM, k = e - KDIM * n;
        float val = 0.f;
        if (n < 36 && k < 100) {
            const int oy = n / 6, ox = n - 6 * oy;
            const int r  = k / 10, c  = k - 10 * r;
            const int ky = r - oy, kx = c - ox;
            if ((unsigned)ky < 5u && (unsigned)kx < 5u)
                val = __ldg(&W[f * 25 + ky * 5 + kx]);
        }
        mt[n * MT_STRIDE + k] = __float2half_rn(val);
    }
    __syncthreads();

    // ---- MMA mainloop ----
    const int w = tid >> 5;                 // warp: batches w*32 .. w*32+31
    const int l = tid & 31;
    const int g = l >> 2, q = l & 3;        // quad row / quad lane

    // ldmatrix.x4.trans address pieces: groups of 8 lanes load the four 8x8
    // tiles M00(m0-7,k0-7), M10(m+8), M01(k+8), M11(both) from [k][m] rows.
    const int grp = l >> 3, gi = l & 7;
    const int krow_off = (grp >= 2) ? 8 : 0;
    const int mcol     = w * 32 + (grp & 1) * 8;
    const uint32_t xwb = smem_u32(xw);

    float d[2][5][4];
#pragma unroll
    for (int t = 0; t < 2; t++)
#pragma unroll
        for (int j = 0; j < 5; j++)
#pragma unroll
            for (int i = 0; i < 4; i++) d[t][j][i] = 0.f;

#pragma unroll
    for (int ks = 0; ks < 7; ks++) {
        const int kb = ks * 16;

        // B fragments: b0 = {B[k0][n], B[k0+1][n]}, b1 = +8 k; n = g + 8j.
        uint32_t b0[5], b1[5];
#pragma unroll
        for (int j = 0; j < 5; j++) {
            const uint32_t* bp = (const uint32_t*)(mt + (j * 8 + g) * MT_STRIDE
                                                      + kb + q * 2);
            b0[j] = bp[0];
            b1[j] = bp[4];
        }

#pragma unroll
        for (int t = 0; t < 2; t++) {
            uint32_t a0, a1, a2, a3;
            const uint32_t addr = xwb +
                (uint32_t)((kb + krow_off + gi) * (XW_STRIDE * 2) +
                           (mcol + t * 16) * 2);
            asm volatile(
                "ldmatrix.sync.aligned.m8n8.x4.trans.shared.b16 "
                "{%0,%1,%2,%3}, [%4];"
                : "=r"(a0), "=r"(a1), "=r"(a2), "=r"(a3) : "r"(addr));
#pragma unroll
            for (int j = 0; j < 5; j++) {
                asm volatile(
                    "mma.sync.aligned.m16n8k16.row.col.f32.f16.f16.f32 "
                    "{%0,%1,%2,%3}, {%4,%5,%6,%7}, {%8,%9}, {%0,%1,%2,%3};"
                    : "+f"(d[t][j][0]), "+f"(d[t][j][1]),
                      "+f"(d[t][j][2]), "+f"(d[t][j][3])
                    : "r"(a0), "r"(a1), "r"(a2), "r"(a3),
                      "r"(b0[j]), "r"(b1[j]));
            }
        }
    }

    // ---- Epilogue: pool 36 outputs -> 2x2 max, + bias, store ----
    const float bv = __ldg(&bias[f]);
#pragma unroll
    for (int t = 0; t < 2; t++) {
        float c0[4], c1[4];                 // rows g / g+8 pool cells
#pragma unroll
        for (int i = 0; i < 4; i++) { c0[i] = -FLT_MAX; c1[i] = -FLT_MAX; }

#pragma unroll
        for (int j = 0; j < 5; j++) {
#pragma unroll
            for (int bn = 0; bn < 2; bn++) {
                const int n = j * 8 + q * 2 + bn;     // runtime (q)
                if (n < 36) {
                    const int oy = n / 6, ox = n - 6 * oy;
                    const int cell = (oy >= 3 ? 2 : 0) + (ox >= 3 ? 1 : 0);
                    const float v0 = d[t][j][bn];
                    const float v1 = d[t][j][2 + bn];
#pragma unroll
                    for (int cc = 0; cc < 4; cc++) {
                        c0[cc] = (cell == cc) ? fmaxf(c0[cc], v0) : c0[cc];
                        c1[cc] = (cell == cc) ? fmaxf(c1[cc], v1) : c1[cc];
                    }
                }
            }
        }
        // quad butterfly: lanes q=0..3 of the same g merge their n-subsets.
#pragma unroll
        for (int delta = 1; delta <= 2; delta <<= 1) {
#pragma unroll
            for (int i = 0; i < 4; i++) {
                c0[i] = fmaxf(c0[i], __shfl_xor_sync(0xffffffffu, c0[i], delta));
                c1[i] = fmaxf(c1[i], __shfl_xor_sync(0xffffffffu, c1[i], delta));
            }
        }
        const int mrow = chunk * MCHUNK + w * 32 + t * 16 + g;
        if (q == 0) {
            float4* o = (float4*)(out + (size_t)mrow * (NF * 4) + f * 4);
            *o = make_float4(c0[0] + bv, c0[1] + bv, c0[2] + bv, c0[3] + bv);
        } else if (q == 1) {
            float4* o = (float4*)(out + (size_t)(mrow + 8) * (NF * 4) + f * 4);
            *o = make_float4(c1[0] + bv, c1[1] + bv, c1[2] + bv, c1[3] + bv);
        }
    }
}

// ---------------------------------------------------------------------------
// kernel_launch: transpose/convert + tensor conv.  Graph-capturable,
// allocation-free (scratch is a zero-initialized __device__ global).
// ---------------------------------------------------------------------------
extern "C" void kernel_launch(void* const* d_in, const int* in_sizes, int n_in,
                              void* d_out, int out_size) {
    (void)in_sizes; (void)n_in; (void)out_size;
    const float* X    = (const float*)d_in[0];
    const float* W    = (const float*)d_in[1];
    const float* bias = (const float*)d_in[2];
    const int*   pos  = (const int*)d_in[3];
    float*       out  = (float*)d_out;

    dim3 tb(32, 8);
    dim3 tg(PIX / 32, BATCH / 64);         // (128, 16)
    xt_transpose_kernel<<<tg, tb>>>(X);

    dim3 cg(NF, BATCH / MCHUNK);           // (1024, 8)
    filters_mma_kernel<<<cg, 128>>>(W, bias, pos, out);
}